// round 1
// baseline (speedup 1.0000x reference)
#include <cuda_runtime.h>
#include <cuda_bf16.h>
#include <cstdint>

#define MAXN 50000
#define MAXE 800000
#define LLAYERS 3

// ---------------- scratch (static device globals; no allocation) ----------------
__device__ float g_h1n[MAXN * 256];      // relu(x@Wn1+bn1)
__device__ float g_ab [MAXN * 256];      // [a | b] per node
__device__ float g_x  [MAXN * 128];      // current node features
__device__ float g_agg[MAXN * 128];      // scatter accumulator
__device__ float g_deg[MAXN];
__device__ float g_Wab [LLAYERS * 256 * 256];
__device__ float g_Wc  [LLAYERS * 128 * 128];
__device__ float g_bc  [LLAYERS * 128];

// ---------------- fused-weight precompute ----------------
// Wab[k][j] : j<128 -> sum_t Wn2[k][t]*Wm1[t][j] ; j>=128 -> sum_t Wn2[k][t]*Wm1[128+t][j-128]
__global__ void fuse_wab(const float* __restrict__ Wn2, const float* __restrict__ Wm1,
                         float* __restrict__ Wab) {
    int idx = blockIdx.x * 256 + threadIdx.x;     // 65536 total
    int k = idx >> 8, j = idx & 255;
    const float* wm = (j < 128) ? (Wm1 + j) : (Wm1 + 128 * 128 + (j - 128));
    float acc = 0.f;
    #pragma unroll 4
    for (int t = 0; t < 128; t++) acc += Wn2[k * 128 + t] * wm[t * 128];
    Wab[idx] = acc;
}

// Wc[k][j] = sum_t We2[k][t] * Wm1[256+t][j]   (k<128, t<64, j<128)
__global__ void fuse_wc(const float* __restrict__ We2, const float* __restrict__ Wm1,
                        float* __restrict__ Wc) {
    int idx = blockIdx.x * 256 + threadIdx.x;     // 16384 total
    int k = idx >> 7, j = idx & 127;
    float acc = 0.f;
    #pragma unroll 4
    for (int t = 0; t < 64; t++) acc += We2[k * 64 + t] * Wm1[(256 + t) * 128 + j];
    Wc[idx] = acc;
}

// bc[j] = bm1[j] + sum_k bn2[k]*(Wm1[k][j]+Wm1[128+k][j]) + sum_t be2[t]*Wm1[256+t][j]
__global__ void fuse_bias(const float* __restrict__ bn2, const float* __restrict__ be2,
                          const float* __restrict__ bm1, const float* __restrict__ Wm1,
                          float* __restrict__ bc) {
    int j = threadIdx.x;
    if (j >= 128) return;
    float acc = bm1[j];
    for (int k = 0; k < 128; k++)
        acc += bn2[k] * (Wm1[k * 128 + j] + Wm1[(128 + k) * 128 + j]);
    for (int t = 0; t < 64; t++)
        acc += be2[t] * Wm1[(256 + t) * 128 + j];
    bc[j] = acc;
}

// ---------------- degree ----------------
__global__ void deg_kernel(const int* __restrict__ dst, float* __restrict__ deg, int E) {
    int e = blockIdx.x * blockDim.x + threadIdx.x;
    if (e < E) atomicAdd(&deg[dst[e]], 1.f);
}

// ---------------- generic tiled GEMM: C = act(A[M,K] @ W[K,Nc] + bias) ----------------
// BM=BN=64, BK=16, 256 threads, 4x4 per thread. Needs K%16==0, Nc%64==0.
template <bool RELU>
__global__ __launch_bounds__(256) void gemm_kernel(
    const float* __restrict__ A, const float* __restrict__ W,
    const float* __restrict__ bias, float* __restrict__ C,
    int M, int K, int Nc)
{
    __shared__ float As[16][68];   // [k][m] transposed, padded
    __shared__ float Ws[16][64];
    int tid = threadIdx.x;
    int bm = blockIdx.y * 64, bn = blockIdx.x * 64;
    int ty = tid >> 4, tx = tid & 15;
    int arow = tid >> 2, akq = tid & 3;
    int wr = tid >> 4, wc = tid & 15;
    float acc[4][4];
    #pragma unroll
    for (int i = 0; i < 4; i++)
        #pragma unroll
        for (int j = 0; j < 4; j++) acc[i][j] = 0.f;

    for (int k0 = 0; k0 < K; k0 += 16) {
        float4 av = make_float4(0.f, 0.f, 0.f, 0.f);
        if (bm + arow < M)
            av = *(const float4*)(A + (size_t)(bm + arow) * K + k0 + 4 * akq);
        As[4 * akq + 0][arow] = av.x;
        As[4 * akq + 1][arow] = av.y;
        As[4 * akq + 2][arow] = av.z;
        As[4 * akq + 3][arow] = av.w;
        float4 wv = *(const float4*)(W + (size_t)(k0 + wr) * Nc + bn + 4 * wc);
        *(float4*)&Ws[wr][4 * wc] = wv;
        __syncthreads();
        #pragma unroll
        for (int kk = 0; kk < 16; kk++) {
            float ra[4];
            #pragma unroll
            for (int i = 0; i < 4; i++) ra[i] = As[kk][ty * 4 + i];
            float4 w4 = *(float4*)&Ws[kk][tx * 4];
            float rw[4] = {w4.x, w4.y, w4.z, w4.w};
            #pragma unroll
            for (int i = 0; i < 4; i++)
                #pragma unroll
                for (int j = 0; j < 4; j++)
                    acc[i][j] = fmaf(ra[i], rw[j], acc[i][j]);
        }
        __syncthreads();
    }
    float b4[4] = {0.f, 0.f, 0.f, 0.f};
    if (bias) {
        b4[0] = bias[bn + tx * 4 + 0];
        b4[1] = bias[bn + tx * 4 + 1];
        b4[2] = bias[bn + tx * 4 + 2];
        b4[3] = bias[bn + tx * 4 + 3];
    }
    #pragma unroll
    for (int i = 0; i < 4; i++) {
        int row = bm + ty * 4 + i;
        if (row < M) {
            float4 o;
            o.x = acc[i][0] + b4[0];
            o.y = acc[i][1] + b4[1];
            o.z = acc[i][2] + b4[2];
            o.w = acc[i][3] + b4[3];
            if (RELU) {
                o.x = fmaxf(o.x, 0.f); o.y = fmaxf(o.y, 0.f);
                o.z = fmaxf(o.z, 0.f); o.w = fmaxf(o.w, 0.f);
            }
            *(float4*)(C + (size_t)row * Nc + bn + tx * 4) = o;
        }
    }
}

// ---------------- persistent fused edge kernel ----------------
// per edge: h1 = relu(ea@We1+be1); hid = relu(h1@Wc + a[dst] + b[src] + bc);
//           out = hid@Wm2; atomicAdd(agg[dst], out)
// tile = 32 edges, 256 threads, weights resident in smem.
#define EDGE_SMEM_FLOATS (8192 + 16384 + 16384 + 2048 + 4096 + 4096 + 128 + 128)
#define EDGE_SMEM_BYTES (EDGE_SMEM_FLOATS * 4 + 64 * 4)

__global__ __launch_bounds__(256) void edge_kernel(
    const float* __restrict__ edge_attr,
    const int* __restrict__ src, const int* __restrict__ dst,
    const float* __restrict__ We1, const float* __restrict__ be1,
    const float* __restrict__ Wc, const float* __restrict__ Wm2,
    const float* __restrict__ biasc, const float* __restrict__ ab,
    float* __restrict__ agg, int E)
{
    extern __shared__ float sm[];
    float* We1s = sm;                // [64][128]
    float* Wcs  = We1s + 8192;       // [128][128]
    float* Wm2s = Wcs + 16384;       // [128][128]
    float* eas  = Wm2s + 16384;      // [32][64]
    float* h1s  = eas + 2048;        // [32][128]
    float* hids = h1s + 4096;        // [32][128]
    float* be1s = hids + 4096;       // [128]
    float* bcs  = be1s + 128;        // [128]
    int* dsts = (int*)(bcs + 128);   // [32]
    int* srcs = dsts + 32;           // [32]

    int tid = threadIdx.x;
    for (int i = tid; i < 2048; i += 256) ((float4*)We1s)[i] = ((const float4*)We1)[i];
    for (int i = tid; i < 4096; i += 256) ((float4*)Wcs)[i]  = ((const float4*)Wc)[i];
    for (int i = tid; i < 4096; i += 256) ((float4*)Wm2s)[i] = ((const float4*)Wm2)[i];
    if (tid < 128) { be1s[tid] = be1[tid]; bcs[tid] = biasc[tid]; }
    __syncthreads();

    int eg = tid >> 5;   // 0..7   (4 edges each)
    int og = tid & 31;   // 0..31  (outputs og, og+32, og+64, og+96)
    int nTiles = (E + 31) >> 5;

    for (int t = blockIdx.x; t < nTiles; t += gridDim.x) {
        int e0 = t << 5;
        if (tid < 32) {
            int e = e0 + tid;
            dsts[tid] = (e < E) ? dst[e] : 0;
            srcs[tid] = (e < E) ? src[e] : 0;
        }
        for (int p = tid; p < 512; p += 256) {
            int r = p >> 4;
            int e = e0 + r;
            float4 v = make_float4(0.f, 0.f, 0.f, 0.f);
            if (e < E) v = ((const float4*)edge_attr)[(size_t)e * 16 + (p & 15)];
            ((float4*)eas)[p] = v;
        }
        __syncthreads();

        float acc[4][4];
        // ---- phase A: h1 = relu(ea @ We1 + be1), K=64 ----
        #pragma unroll
        for (int i = 0; i < 4; i++)
            #pragma unroll
            for (int j = 0; j < 4; j++) acc[i][j] = 0.f;
        #pragma unroll 4
        for (int k = 0; k < 64; k++) {
            float ra[4], rw[4];
            #pragma unroll
            for (int i = 0; i < 4; i++) ra[i] = eas[(eg * 4 + i) * 64 + k];
            #pragma unroll
            for (int j = 0; j < 4; j++) rw[j] = We1s[k * 128 + og + 32 * j];
            #pragma unroll
            for (int i = 0; i < 4; i++)
                #pragma unroll
                for (int j = 0; j < 4; j++)
                    acc[i][j] = fmaf(ra[i], rw[j], acc[i][j]);
        }
        #pragma unroll
        for (int i = 0; i < 4; i++)
            #pragma unroll
            for (int j = 0; j < 4; j++) {
                int o = og + 32 * j;
                h1s[(eg * 4 + i) * 128 + o] = fmaxf(acc[i][j] + be1s[o], 0.f);
            }
        __syncthreads();

        // ---- phase B: hid = relu(h1 @ Wc + a[dst] + b[src] + bc), K=128 ----
        #pragma unroll
        for (int i = 0; i < 4; i++)
            #pragma unroll
            for (int j = 0; j < 4; j++) acc[i][j] = 0.f;
        #pragma unroll 4
        for (int k = 0; k < 128; k++) {
            float ra[4], rw[4];
            #pragma unroll
            for (int i = 0; i < 4; i++) ra[i] = h1s[(eg * 4 + i) * 128 + k];
            #pragma unroll
            for (int j = 0; j < 4; j++) rw[j] = Wcs[k * 128 + og + 32 * j];
            #pragma unroll
            for (int i = 0; i < 4; i++)
                #pragma unroll
                for (int j = 0; j < 4; j++)
                    acc[i][j] = fmaf(ra[i], rw[j], acc[i][j]);
        }
        #pragma unroll
        for (int i = 0; i < 4; i++) {
            int d = dsts[eg * 4 + i], s = srcs[eg * 4 + i];
            const float* arow = ab + (size_t)d * 256;
            const float* brow = ab + (size_t)s * 256 + 128;
            #pragma unroll
            for (int j = 0; j < 4; j++) {
                int o = og + 32 * j;
                hids[(eg * 4 + i) * 128 + o] =
                    fmaxf(acc[i][j] + arow[o] + brow[o] + bcs[o], 0.f);
            }
        }
        __syncthreads();

        // ---- phase C: out = hid @ Wm2; atomic scatter, K=128 ----
        #pragma unroll
        for (int i = 0; i < 4; i++)
            #pragma unroll
            for (int j = 0; j < 4; j++) acc[i][j] = 0.f;
        #pragma unroll 4
        for (int k = 0; k < 128; k++) {
            float ra[4], rw[4];
            #pragma unroll
            for (int i = 0; i < 4; i++) ra[i] = hids[(eg * 4 + i) * 128 + k];
            #pragma unroll
            for (int j = 0; j < 4; j++) rw[j] = Wm2s[k * 128 + og + 32 * j];
            #pragma unroll
            for (int i = 0; i < 4; i++)
                #pragma unroll
                for (int j = 0; j < 4; j++)
                    acc[i][j] = fmaf(ra[i], rw[j], acc[i][j]);
        }
        #pragma unroll
        for (int i = 0; i < 4; i++) {
            int e = e0 + eg * 4 + i;
            if (e < E) {
                float* arow = agg + (size_t)dsts[eg * 4 + i] * 128;
                #pragma unroll
                for (int j = 0; j < 4; j++)
                    atomicAdd(arow + og + 32 * j, acc[i][j]);
            }
        }
        __syncthreads();
    }
}

// ---------------- LayerNorm + relu (+ mean-div + bm2 gate) ----------------
__global__ void ln_kernel(const float* __restrict__ agg, const float* __restrict__ deg,
                          const float* __restrict__ bm2, const float* __restrict__ lnw,
                          const float* __restrict__ lnb, float* __restrict__ xout, int N)
{
    int gwarp = (blockIdx.x * blockDim.x + threadIdx.x) >> 5;
    int lane = threadIdx.x & 31;
    if (gwarp >= N) return;
    float d = deg[gwarp];
    float inv = 1.f / fmaxf(d, 1.f);
    float add = (d > 0.f) ? 1.f : 0.f;
    float4 v = ((const float4*)agg)[(size_t)gwarp * 32 + lane];
    float4 b = ((const float4*)bm2)[lane];
    v.x = v.x * inv + add * b.x;
    v.y = v.y * inv + add * b.y;
    v.z = v.z * inv + add * b.z;
    v.w = v.w * inv + add * b.w;
    float s = v.x + v.y + v.z + v.w;
    #pragma unroll
    for (int o = 16; o; o >>= 1) s += __shfl_xor_sync(0xffffffffu, s, o);
    float mu = s * (1.f / 128.f);
    float d0 = v.x - mu, d1 = v.y - mu, d2 = v.z - mu, d3 = v.w - mu;
    float q = d0 * d0 + d1 * d1 + d2 * d2 + d3 * d3;
    #pragma unroll
    for (int o = 16; o; o >>= 1) q += __shfl_xor_sync(0xffffffffu, q, o);
    float rs = rsqrtf(q * (1.f / 128.f) + 1e-5f);
    float4 w = ((const float4*)lnw)[lane];
    float4 bb = ((const float4*)lnb)[lane];
    float4 o;
    o.x = fmaxf(d0 * rs * w.x + bb.x, 0.f);
    o.y = fmaxf(d1 * rs * w.y + bb.y, 0.f);
    o.z = fmaxf(d2 * rs * w.z + bb.z, 0.f);
    o.w = fmaxf(d3 * rs * w.w + bb.w, 0.f);
    ((float4*)xout)[(size_t)gwarp * 32 + lane] = o;
}

// ---------------- host ----------------
extern "C" void kernel_launch(void* const* d_in, const int* in_sizes, int n_in,
                              void* d_out, int out_size)
{
    const float* x        = (const float*)d_in[0];
    const float* ea       = (const float*)d_in[1];
    const int*   eidx     = (const int*)  d_in[2];
    const float* Wn1      = (const float*)d_in[3];
    const float* bn1      = (const float*)d_in[4];
    const float* Wn2      = (const float*)d_in[5];
    const float* bn2      = (const float*)d_in[6];
    const float* We1      = (const float*)d_in[7];
    const float* be1      = (const float*)d_in[8];
    const float* We2      = (const float*)d_in[9];
    const float* be2      = (const float*)d_in[10];
    const float* Wm1      = (const float*)d_in[11];
    const float* bm1      = (const float*)d_in[12];
    const float* Wm2      = (const float*)d_in[13];
    const float* bm2      = (const float*)d_in[14];
    const float* lnw      = (const float*)d_in[15];
    const float* lnb      = (const float*)d_in[16];
    const float* Wf       = (const float*)d_in[17];
    const float* bf       = (const float*)d_in[18];

    int N = in_sizes[0] / 128;
    int E = in_sizes[1] / 64;
    const int* srcp = eidx;
    const int* dstp = eidx + E;

    float *h1n, *ab, *xb, *agg, *deg, *Wab, *Wc, *bc;
    cudaGetSymbolAddress((void**)&h1n, g_h1n);
    cudaGetSymbolAddress((void**)&ab,  g_ab);
    cudaGetSymbolAddress((void**)&xb,  g_x);
    cudaGetSymbolAddress((void**)&agg, g_agg);
    cudaGetSymbolAddress((void**)&deg, g_deg);
    cudaGetSymbolAddress((void**)&Wab, g_Wab);
    cudaGetSymbolAddress((void**)&Wc,  g_Wc);
    cudaGetSymbolAddress((void**)&bc,  g_bc);

    cudaFuncSetAttribute(edge_kernel, cudaFuncAttributeMaxDynamicSharedMemorySize,
                         EDGE_SMEM_BYTES);

    // degree (once per launch)
    cudaMemsetAsync(deg, 0, (size_t)N * sizeof(float));
    deg_kernel<<<(E + 255) / 256, 256>>>(dstp, deg, E);

    // fused weights for all layers
    for (int l = 0; l < LLAYERS; l++) {
        fuse_wab<<<256, 256>>>(Wn2 + (size_t)l * 256 * 128, Wm1 + (size_t)l * 320 * 128,
                               Wab + (size_t)l * 256 * 256);
        fuse_wc<<<64, 256>>>(We2 + (size_t)l * 128 * 64, Wm1 + (size_t)l * 320 * 128,
                             Wc + (size_t)l * 128 * 128);
        fuse_bias<<<1, 128>>>(bn2 + l * 128, be2 + l * 64, bm1 + l * 128,
                              Wm1 + (size_t)l * 320 * 128, bc + l * 128);
    }

    const float* curx = x;
    dim3 gN256(256 / 64, (N + 63) / 64);
    for (int l = 0; l < LLAYERS; l++) {
        // h1n = relu(x @ Wn1 + bn1)          [N,256]
        gemm_kernel<true><<<gN256, 256>>>(curx, Wn1 + (size_t)l * 128 * 256,
                                          bn1 + l * 256, h1n, N, 128, 256);
        // ab = h1n @ Wab                      [N,256] = [a | b]
        gemm_kernel<false><<<gN256, 256>>>(h1n, Wab + (size_t)l * 256 * 256,
                                           (const float*)nullptr, ab, N, 256, 256);
        cudaMemsetAsync(agg, 0, (size_t)N * 128 * sizeof(float));
        edge_kernel<<<152, 256, EDGE_SMEM_BYTES>>>(
            ea, srcp, dstp,
            We1 + (size_t)l * 64 * 128, be1 + l * 128,
            Wc + (size_t)l * 128 * 128, Wm2 + (size_t)l * 128 * 128,
            bc + l * 128, ab, agg, E);
        ln_kernel<<<(N + 7) / 8, 256>>>(agg, deg, bm2 + l * 128, lnw + l * 128,
                                        lnb + l * 128, xb, N);
        curx = xb;
    }
    // final: out = x @ Wf + bf               [N,64]
    dim3 gF(1, (N + 63) / 64);
    gemm_kernel<false><<<gF, 256>>>(curx, Wf, bf, (float*)d_out, N, 128, 64);
}

// round 3
// speedup vs baseline: 3.1908x; 3.1908x over previous
#include <cuda_runtime.h>
#include <cuda_bf16.h>
#include <cstdint>

#define MAXN 50000
#define MAXE 800000
#define LLAYERS 3

// ================= helpers =================
__device__ __forceinline__ uint32_t packbf(float lo_v, float hi_v) {
    // result: lower 16 bits = bf16(lo_v), upper = bf16(hi_v)
    uint32_t r;
    asm("cvt.rn.satfinite.bf16x2.f32 %0, %1, %2;" : "=r"(r) : "f"(hi_v), "f"(lo_v));
    return r;
}
__device__ __forceinline__ float bfl(uint32_t p) { return __uint_as_float(p << 16); }
__device__ __forceinline__ float bfh(uint32_t p) { return __uint_as_float(p & 0xffff0000u); }

__device__ __forceinline__ void pack_hl(float v0, float v1, uint32_t& h, uint32_t& l) {
    h = packbf(v0, v1);
    l = packbf(v0 - bfl(h), v1 - bfh(h));
}

__device__ __forceinline__ void mma_bf16(float* c, const uint32_t* a, uint32_t b0, uint32_t b1) {
    asm volatile(
        "mma.sync.aligned.m16n8k16.row.col.f32.bf16.bf16.f32 "
        "{%0,%1,%2,%3}, {%4,%5,%6,%7}, {%8,%9}, {%0,%1,%2,%3};\n"
        : "+f"(c[0]), "+f"(c[1]), "+f"(c[2]), "+f"(c[3])
        : "r"(a[0]), "r"(a[1]), "r"(a[2]), "r"(a[3]), "r"(b0), "r"(b1));
}

// ================= scratch (static device globals) =================
__device__ float g_h1n[MAXN * 256];
__device__ float g_ab [MAXN * 256];
__device__ float g_x  [MAXN * 128];
__device__ float g_agg[MAXN * 128];
__device__ float g_deg[MAXN];
__device__ float g_Wab [LLAYERS * 256 * 256];
__device__ float g_Wc  [LLAYERS * 128 * 128];
__device__ float g_bc  [LLAYERS * 128];
// per-layer packed bf16 transposed (padded) weights, 88064 bf16 elems / layer:
// [We1h 128x72][We1l 128x72][Wch 128x136][Wcl 128x136][Wm2h 128x136][Wm2l 128x136]
#define WP_LAYER_ELEMS 88064
__device__ uint4 g_wpack[LLAYERS * WP_LAYER_ELEMS * 2 / 16];

// elem offsets within a layer
#define WO_WE1H 0
#define WO_WE1L 9216
#define WO_WCH  18432
#define WO_WCL  35840
#define WO_WM2H 53248
#define WO_WM2L 70656

// ================= weight fuse kernels =================
__global__ void fuse_wab(const float* __restrict__ Wn2, const float* __restrict__ Wm1,
                         float* __restrict__ Wab) {
    int idx = blockIdx.x * 256 + threadIdx.x;
    int k = idx >> 8, j = idx & 255;
    const float* wm = (j < 128) ? (Wm1 + j) : (Wm1 + 128 * 128 + (j - 128));
    float acc = 0.f;
    #pragma unroll 4
    for (int t = 0; t < 128; t++) acc += Wn2[k * 128 + t] * wm[t * 128];
    Wab[idx] = acc;
}

__global__ void fuse_wc(const float* __restrict__ We2, const float* __restrict__ Wm1,
                        float* __restrict__ Wc) {
    int idx = blockIdx.x * 256 + threadIdx.x;
    int k = idx >> 7, j = idx & 127;
    float acc = 0.f;
    #pragma unroll 4
    for (int t = 0; t < 64; t++) acc += We2[k * 64 + t] * Wm1[(256 + t) * 128 + j];
    Wc[idx] = acc;
}

__global__ void fuse_bias(const float* __restrict__ bn2, const float* __restrict__ be2,
                          const float* __restrict__ bm1, const float* __restrict__ Wm1,
                          float* __restrict__ bc) {
    int j = threadIdx.x;
    if (j >= 128) return;
    float acc = bm1[j];
    for (int k = 0; k < 128; k++)
        acc += bn2[k] * (Wm1[k * 128 + j] + Wm1[(128 + k) * 128 + j]);
    for (int t = 0; t < 64; t++)
        acc += be2[t] * Wm1[(256 + t) * 128 + j];
    bc[j] = acc;
}

// ================= bf16 hi/lo transposed weight prep (row-padded) =================
// We1T: out[n][k] = We1[k*128+n], n<128, k<64, row pitch 72
__global__ void prep_we1t(const float* __restrict__ We1, __nv_bfloat16* __restrict__ hi,
                          __nv_bfloat16* __restrict__ lo) {
    int idx = blockIdx.x * 256 + threadIdx.x;   // 8192
    int n = idx >> 6, k = idx & 63;
    float w = We1[k * 128 + n];
    __nv_bfloat16 h = __float2bfloat16(w);
    float r = w - __bfloat162float(h);
    hi[n * 72 + k] = h;
    lo[n * 72 + k] = __float2bfloat16(r);
}

// W128T: out[n][k] = W[k*128+n], n<128, k<128, row pitch 136
__global__ void prep_w128t(const float* __restrict__ W, __nv_bfloat16* __restrict__ hi,
                           __nv_bfloat16* __restrict__ lo) {
    int idx = blockIdx.x * 256 + threadIdx.x;   // 16384
    int n = idx >> 7, k = idx & 127;
    float w = W[k * 128 + n];
    __nv_bfloat16 h = __float2bfloat16(w);
    float r = w - __bfloat162float(h);
    hi[n * 136 + k] = h;
    lo[n * 136 + k] = __float2bfloat16(r);
}

// ================= degree =================
__global__ void deg_kernel(const int* __restrict__ dst, float* __restrict__ deg, int E) {
    int e = blockIdx.x * blockDim.x + threadIdx.x;
    if (e < E) atomicAdd(&deg[dst[e]], 1.f);
}

// ================= fp32 SIMT GEMM for node side =================
template <bool RELU>
__global__ __launch_bounds__(256) void gemm_kernel(
    const float* __restrict__ A, const float* __restrict__ W,
    const float* __restrict__ bias, float* __restrict__ C,
    int M, int K, int Nc)
{
    __shared__ float As[16][68];
    __shared__ float Ws[16][64];
    int tid = threadIdx.x;
    int bm = blockIdx.y * 64, bn = blockIdx.x * 64;
    int ty = tid >> 4, tx = tid & 15;
    int arow = tid >> 2, akq = tid & 3;
    int wr = tid >> 4, wc = tid & 15;
    float acc[4][4];
    #pragma unroll
    for (int i = 0; i < 4; i++)
        #pragma unroll
        for (int j = 0; j < 4; j++) acc[i][j] = 0.f;

    for (int k0 = 0; k0 < K; k0 += 16) {
        float4 av = make_float4(0.f, 0.f, 0.f, 0.f);
        if (bm + arow < M)
            av = *(const float4*)(A + (size_t)(bm + arow) * K + k0 + 4 * akq);
        As[4 * akq + 0][arow] = av.x;
        As[4 * akq + 1][arow] = av.y;
        As[4 * akq + 2][arow] = av.z;
        As[4 * akq + 3][arow] = av.w;
        float4 wv = *(const float4*)(W + (size_t)(k0 + wr) * Nc + bn + 4 * wc);
        *(float4*)&Ws[wr][4 * wc] = wv;
        __syncthreads();
        #pragma unroll
        for (int kk = 0; kk < 16; kk++) {
            float ra[4];
            #pragma unroll
            for (int i = 0; i < 4; i++) ra[i] = As[kk][ty * 4 + i];
            float4 w4 = *(float4*)&Ws[kk][tx * 4];
            float rw[4] = {w4.x, w4.y, w4.z, w4.w};
            #pragma unroll
            for (int i = 0; i < 4; i++)
                #pragma unroll
                for (int j = 0; j < 4; j++)
                    acc[i][j] = fmaf(ra[i], rw[j], acc[i][j]);
        }
        __syncthreads();
    }
    float b4[4] = {0.f, 0.f, 0.f, 0.f};
    if (bias) {
        b4[0] = bias[bn + tx * 4 + 0];
        b4[1] = bias[bn + tx * 4 + 1];
        b4[2] = bias[bn + tx * 4 + 2];
        b4[3] = bias[bn + tx * 4 + 3];
    }
    #pragma unroll
    for (int i = 0; i < 4; i++) {
        int row = bm + ty * 4 + i;
        if (row < M) {
            float4 o;
            o.x = acc[i][0] + b4[0];
            o.y = acc[i][1] + b4[1];
            o.z = acc[i][2] + b4[2];
            o.w = acc[i][3] + b4[3];
            if (RELU) {
                o.x = fmaxf(o.x, 0.f); o.y = fmaxf(o.y, 0.f);
                o.z = fmaxf(o.z, 0.f); o.w = fmaxf(o.w, 0.f);
            }
            *(float4*)(C + (size_t)row * Nc + bn + tx * 4) = o;
        }
    }
}

// ================= mma.sync fused edge kernel =================
// SMEM: weights (176128 B) + be1s (512) + bcs (512)
#define EDGE3_SMEM (176128 + 1024)

// one stage: acc[16][4] += A(hi/lo) @ W(hi/lo), NC k16-chunks
template<int NC>
__device__ __forceinline__ void stage_mma(
    float acc[16][4], const uint32_t Ah[8][4], const uint32_t Al[8][4],
    const __nv_bfloat16* __restrict__ Wh, const __nv_bfloat16* __restrict__ Wl,
    int KP, int qr, int qc)
{
    #pragma unroll
    for (int j = 0; j < NC; j++) {
        #pragma unroll
        for (int nb = 0; nb < 16; nb++) {
            const __nv_bfloat16* ph = Wh + (8 * nb + qr) * KP + 16 * j + qc;
            const __nv_bfloat16* pl = Wl + (8 * nb + qr) * KP + 16 * j + qc;
            uint32_t bh0 = *(const uint32_t*)ph;
            uint32_t bh1 = *(const uint32_t*)(ph + 8);
            uint32_t bl0 = *(const uint32_t*)pl;
            uint32_t bl1 = *(const uint32_t*)(pl + 8);
            mma_bf16(acc[nb], Ah[j], bh0, bh1);
            mma_bf16(acc[nb], Ah[j], bl0, bl1);
            mma_bf16(acc[nb], Al[j], bh0, bh1);
        }
    }
}

__global__ __launch_bounds__(256) void edge_kernel3(
    const float* __restrict__ ea,
    const int* __restrict__ src, const int* __restrict__ dst,
    const uint4* __restrict__ wpack,
    const float* __restrict__ be1, const float* __restrict__ bc,
    const float* __restrict__ ab, float* __restrict__ agg, int E)
{
    extern __shared__ char smem[];
    __nv_bfloat16* W = (__nv_bfloat16*)smem;
    float* be1s = (float*)(smem + 176128);
    float* bcs  = (float*)(smem + 176128 + 512);

    int tid = threadIdx.x;
    // load packed weights linearly (176128 B = 11008 uint4)
    {
        uint4* s4 = (uint4*)smem;
        for (int i = tid; i < 11008; i += 256) s4[i] = wpack[i];
        if (tid < 128) { be1s[tid] = be1[tid]; bcs[tid] = bc[tid]; }
    }
    __syncthreads();

    const __nv_bfloat16* We1h = W + WO_WE1H;
    const __nv_bfloat16* We1l = W + WO_WE1L;
    const __nv_bfloat16* Wch  = W + WO_WCH;
    const __nv_bfloat16* Wcl  = W + WO_WCL;
    const __nv_bfloat16* Wm2h = W + WO_WM2H;
    const __nv_bfloat16* Wm2l = W + WO_WM2L;

    int lane = tid & 31, wid = tid >> 5;
    int qr = lane >> 2;          // 0..7
    int qc = (lane & 3) * 2;     // 0,2,4,6

    int nG = (E + 15) >> 4;
    for (int g = blockIdx.x * 8 + wid; g < nG; g += gridDim.x * 8) {
        int e0 = g << 4;
        int er0 = e0 + qr, er1 = er0 + 8;
        bool v0 = er0 < E, v1 = er1 < E;
        int ec0 = v0 ? er0 : 0, ec1 = v1 ? er1 : 0;
        int d0 = dst[ec0], d1 = dst[ec1];
        int s0 = src[ec0], s1 = src[ec1];

        uint32_t Ah[8][4], Al[8][4];
        float acc[16][4];

        // ---- load ea fragments (K=64, 4 chunks) ----
        #pragma unroll
        for (int j = 0; j < 4; j++) {
            const float* r0p = ea + (size_t)ec0 * 64 + 16 * j + qc;
            const float* r1p = ea + (size_t)ec1 * 64 + 16 * j + qc;
            float2 x0 = *(const float2*)r0p;
            float2 x1 = *(const float2*)r1p;
            float2 x2 = *(const float2*)(r0p + 8);
            float2 x3 = *(const float2*)(r1p + 8);
            pack_hl(x0.x, x0.y, Ah[j][0], Al[j][0]);
            pack_hl(x1.x, x1.y, Ah[j][1], Al[j][1]);
            pack_hl(x2.x, x2.y, Ah[j][2], Al[j][2]);
            pack_hl(x3.x, x3.y, Ah[j][3], Al[j][3]);
        }

        // ---- S1: h1 = relu(ea @ We1T + be1) ----
        #pragma unroll
        for (int nb = 0; nb < 16; nb++)
            #pragma unroll
            for (int q = 0; q < 4; q++) acc[nb][q] = 0.f;
        stage_mma<4>(acc, Ah, Al, We1h, We1l, 72, qr, qc);
        #pragma unroll
        for (int nb = 0; nb < 16; nb++) {
            int col = 8 * nb + qc;
            float b0 = be1s[col], b1 = be1s[col + 1];
            float u0 = fmaxf(acc[nb][0] + b0, 0.f);
            float u1 = fmaxf(acc[nb][1] + b1, 0.f);
            float u2 = fmaxf(acc[nb][2] + b0, 0.f);
            float u3 = fmaxf(acc[nb][3] + b1, 0.f);
            int j = nb >> 1, q = (nb & 1) * 2;
            pack_hl(u0, u1, Ah[j][q],     Al[j][q]);
            pack_hl(u2, u3, Ah[j][q + 1], Al[j][q + 1]);
        }

        // ---- S2: hid = relu(h1 @ WcT + a[dst] + b[src] + bc) ----
        #pragma unroll
        for (int nb = 0; nb < 16; nb++)
            #pragma unroll
            for (int q = 0; q < 4; q++) acc[nb][q] = 0.f;
        stage_mma<8>(acc, Ah, Al, Wch, Wcl, 136, qr, qc);
        {
            const float* a0p = ab + (size_t)d0 * 256;
            const float* a1p = ab + (size_t)d1 * 256;
            const float* b0p = ab + (size_t)s0 * 256 + 128;
            const float* b1p = ab + (size_t)s1 * 256 + 128;
            #pragma unroll
            for (int nb = 0; nb < 16; nb++) {
                int col = 8 * nb + qc;
                float2 ga0 = *(const float2*)(a0p + col);
                float2 ga1 = *(const float2*)(a1p + col);
                float2 gb0 = *(const float2*)(b0p + col);
                float2 gb1 = *(const float2*)(b1p + col);
                float bc0 = bcs[col], bc1 = bcs[col + 1];
                float u0 = fmaxf(acc[nb][0] + ga0.x + gb0.x + bc0, 0.f);
                float u1 = fmaxf(acc[nb][1] + ga0.y + gb0.y + bc1, 0.f);
                float u2 = fmaxf(acc[nb][2] + ga1.x + gb1.x + bc0, 0.f);
                float u3 = fmaxf(acc[nb][3] + ga1.y + gb1.y + bc1, 0.f);
                int j = nb >> 1, q = (nb & 1) * 2;
                pack_hl(u0, u1, Ah[j][q],     Al[j][q]);
                pack_hl(u2, u3, Ah[j][q + 1], Al[j][q + 1]);
            }
        }

        // ---- S3: out = hid @ Wm2T; scatter ----
        #pragma unroll
        for (int nb = 0; nb < 16; nb++)
            #pragma unroll
            for (int q = 0; q < 4; q++) acc[nb][q] = 0.f;
        stage_mma<8>(acc, Ah, Al, Wm2h, Wm2l, 136, qr, qc);
        {
            float* g0 = agg + (size_t)d0 * 128;
            float* g1 = agg + (size_t)d1 * 128;
            #pragma unroll
            for (int nb = 0; nb < 16; nb++) {
                int col = 8 * nb + qc;
                if (v0)
                    asm volatile("red.global.add.v2.f32 [%0], {%1, %2};"
                                 :: "l"(g0 + col), "f"(acc[nb][0]), "f"(acc[nb][1]) : "memory");
                if (v1)
                    asm volatile("red.global.add.v2.f32 [%0], {%1, %2};"
                                 :: "l"(g1 + col), "f"(acc[nb][2]), "f"(acc[nb][3]) : "memory");
            }
        }
    }
}

// ================= LayerNorm + relu =================
__global__ void ln_kernel(const float* __restrict__ agg, const float* __restrict__ deg,
                          const float* __restrict__ bm2, const float* __restrict__ lnw,
                          const float* __restrict__ lnb, float* __restrict__ xout, int N)
{
    int gwarp = (blockIdx.x * blockDim.x + threadIdx.x) >> 5;
    int lane = threadIdx.x & 31;
    if (gwarp >= N) return;
    float d = deg[gwarp];
    float inv = 1.f / fmaxf(d, 1.f);
    float add = (d > 0.f) ? 1.f : 0.f;
    float4 v = ((const float4*)agg)[(size_t)gwarp * 32 + lane];
    float4 b = ((const float4*)bm2)[lane];
    v.x = v.x * inv + add * b.x;
    v.y = v.y * inv + add * b.y;
    v.z = v.z * inv + add * b.z;
    v.w = v.w * inv + add * b.w;
    float s = v.x + v.y + v.z + v.w;
    #pragma unroll
    for (int o = 16; o; o >>= 1) s += __shfl_xor_sync(0xffffffffu, s, o);
    float mu = s * (1.f / 128.f);
    float d0 = v.x - mu, d1 = v.y - mu, d2 = v.z - mu, d3 = v.w - mu;
    float q = d0 * d0 + d1 * d1 + d2 * d2 + d3 * d3;
    #pragma unroll
    for (int o = 16; o; o >>= 1) q += __shfl_xor_sync(0xffffffffu, q, o);
    float rs = rsqrtf(q * (1.f / 128.f) + 1e-5f);
    float4 w = ((const float4*)lnw)[lane];
    float4 bb = ((const float4*)lnb)[lane];
    float4 o;
    o.x = fmaxf(d0 * rs * w.x + bb.x, 0.f);
    o.y = fmaxf(d1 * rs * w.y + bb.y, 0.f);
    o.z = fmaxf(d2 * rs * w.z + bb.z, 0.f);
    o.w = fmaxf(d3 * rs * w.w + bb.w, 0.f);
    ((float4*)xout)[(size_t)gwarp * 32 + lane] = o;
}

// ================= host =================
extern "C" void kernel_launch(void* const* d_in, const int* in_sizes, int n_in,
                              void* d_out, int out_size)
{
    const float* x    = (const float*)d_in[0];
    const float* ea   = (const float*)d_in[1];
    const int*   eidx = (const int*)  d_in[2];
    const float* Wn1  = (const float*)d_in[3];
    const float* bn1  = (const float*)d_in[4];
    const float* Wn2  = (const float*)d_in[5];
    const float* bn2  = (const float*)d_in[6];
    const float* We1  = (const float*)d_in[7];
    const float* be1  = (const float*)d_in[8];
    const float* We2  = (const float*)d_in[9];
    const float* be2  = (const float*)d_in[10];
    const float* Wm1  = (const float*)d_in[11];
    const float* bm1  = (const float*)d_in[12];
    const float* Wm2  = (const float*)d_in[13];
    const float* bm2  = (const float*)d_in[14];
    const float* lnw  = (const float*)d_in[15];
    const float* lnb  = (const float*)d_in[16];
    const float* Wf   = (const float*)d_in[17];
    const float* bf   = (const float*)d_in[18];

    int N = in_sizes[0] / 128;
    int E = in_sizes[1] / 64;
    const int* srcp = eidx;
    const int* dstp = eidx + E;

    float *h1n, *ab, *xb, *agg, *deg, *Wab, *Wc, *bc;
    uint4* wpack;
    cudaGetSymbolAddress((void**)&h1n, g_h1n);
    cudaGetSymbolAddress((void**)&ab,  g_ab);
    cudaGetSymbolAddress((void**)&xb,  g_x);
    cudaGetSymbolAddress((void**)&agg, g_agg);
    cudaGetSymbolAddress((void**)&deg, g_deg);
    cudaGetSymbolAddress((void**)&Wab, g_Wab);
    cudaGetSymbolAddress((void**)&Wc,  g_Wc);
    cudaGetSymbolAddress((void**)&bc,  g_bc);
    cudaGetSymbolAddress((void**)&wpack, g_wpack);
    __nv_bfloat16* wb = (__nv_bfloat16*)wpack;

    cudaFuncSetAttribute(edge_kernel3, cudaFuncAttributeMaxDynamicSharedMemorySize,
                         EDGE3_SMEM);

    cudaMemsetAsync(deg, 0, (size_t)N * sizeof(float));
    deg_kernel<<<(E + 255) / 256, 256>>>(dstp, deg, E);

    for (int l = 0; l < LLAYERS; l++) {
        fuse_wab<<<256, 256>>>(Wn2 + (size_t)l * 256 * 128, Wm1 + (size_t)l * 320 * 128,
                               Wab + (size_t)l * 256 * 256);
        fuse_wc<<<64, 256>>>(We2 + (size_t)l * 128 * 64, Wm1 + (size_t)l * 320 * 128,
                             Wc + (size_t)l * 128 * 128);
        fuse_bias<<<1, 128>>>(bn2 + l * 128, be2 + l * 64, bm1 + l * 128,
                              Wm1 + (size_t)l * 320 * 128, bc + l * 128);
        __nv_bfloat16* base = wb + (size_t)l * WP_LAYER_ELEMS;
        prep_we1t<<<32, 256>>>(We1 + (size_t)l * 64 * 128,
                               base + WO_WE1H, base + WO_WE1L);
        prep_w128t<<<64, 256>>>(Wc + (size_t)l * 128 * 128,
                                base + WO_WCH, base + WO_WCL);
        prep_w128t<<<64, 256>>>(Wm2 + (size_t)l * 128 * 128,
                                base + WO_WM2H, base + WO_WM2L);
    }

    const float* curx = x;
    dim3 gN256(256 / 64, (N + 63) / 64);
    for (int l = 0; l < LLAYERS; l++) {
        gemm_kernel<true><<<gN256, 256>>>(curx, Wn1 + (size_t)l * 128 * 256,
                                          bn1 + l * 256, h1n, N, 128, 256);
        gemm_kernel<false><<<gN256, 256>>>(h1n, Wab + (size_t)l * 256 * 256,
                                           (const float*)nullptr, ab, N, 256, 256);
        cudaMemsetAsync(agg, 0, (size_t)N * 128 * sizeof(float));
        edge_kernel3<<<148, 256, EDGE3_SMEM>>>(
            ea, srcp, dstp,
            (const uint4*)(wb + (size_t)l * WP_LAYER_ELEMS),
            be1 + l * 128, bc + l * 128, ab, agg, E);
        ln_kernel<<<(N + 7) / 8, 256>>>(agg, deg, bm2 + l * 128, lnw + l * 128,
                                        lnb + l * 128, xb, N);
        curx = xb;
    }
    dim3 gF(1, (N + 63) / 64);
    gemm_kernel<false><<<gF, 256>>>(curx, Wf, bf, (float*)d_out, N, 128, 64);
}

// round 4
// speedup vs baseline: 3.8225x; 1.1980x over previous
#include <cuda_runtime.h>
#include <cuda_bf16.h>
#include <cstdint>

#define MAXN 50000
#define MAXE 800000
#define LLAYERS 3

// ================= helpers =================
__device__ __forceinline__ uint32_t packbf(float lo_v, float hi_v) {
    // result: lower 16 bits = bf16(lo_v), upper = bf16(hi_v)
    uint32_t r;
    asm("cvt.rn.satfinite.bf16x2.f32 %0, %1, %2;" : "=r"(r) : "f"(hi_v), "f"(lo_v));
    return r;
}
__device__ __forceinline__ float bfl(uint32_t p) { return __uint_as_float(p << 16); }
__device__ __forceinline__ float bfh(uint32_t p) { return __uint_as_float(p & 0xffff0000u); }

__device__ __forceinline__ void pack_hl(float v0, float v1, uint32_t& h, uint32_t& l) {
    h = packbf(v0, v1);
    l = packbf(v0 - bfl(h), v1 - bfh(h));
}

__device__ __forceinline__ void mma_bf16(float* c, const uint32_t* a, uint32_t b0, uint32_t b1) {
    asm volatile(
        "mma.sync.aligned.m16n8k16.row.col.f32.bf16.bf16.f32 "
        "{%0,%1,%2,%3}, {%4,%5,%6,%7}, {%8,%9}, {%0,%1,%2,%3};\n"
        : "+f"(c[0]), "+f"(c[1]), "+f"(c[2]), "+f"(c[3])
        : "r"(a[0]), "r"(a[1]), "r"(a[2]), "r"(a[3]), "r"(b0), "r"(b1));
}

// ================= scratch (static device globals) =================
__device__ float g_h1n[MAXN * 256];
__device__ float g_ab [MAXN * 256];
__device__ float g_x  [MAXN * 128];
__device__ float g_agg[MAXN * 128];
__device__ float g_deg[MAXN];
__device__ float g_Wab [LLAYERS * 256 * 256];
__device__ float g_Wc  [LLAYERS * 128 * 128];
__device__ float g_bc  [LLAYERS * 128];
// per-layer packed bf16 transposed (padded) edge weights, 88064 bf16 elems / layer:
// [We1h 128x72][We1l 128x72][Wch 128x136][Wcl 128x136][Wm2h 128x136][Wm2l 128x136]
#define WP_LAYER_ELEMS 88064
__device__ uint4 g_wpack[LLAYERS * WP_LAYER_ELEMS * 2 / 16];

// per-layer packed bf16 transposed node weights:
// [W1hi 256x136][W1lo 256x136][WABhi 256x264][WABlo 256x264] = 204800 elems
#define NP_LAYER_ELEMS 204800
#define NP_W1  0
#define NP_WAB 69632
__device__ uint4 g_wnode[LLAYERS * NP_LAYER_ELEMS * 2 / 16];
// Wf packed: [hi 64x136][lo 64x136]
__device__ uint4 g_wf[2 * 64 * 136 * 2 / 16];

// elem offsets within an edge-weight layer
#define WO_WE1H 0
#define WO_WE1L 9216
#define WO_WCH  18432
#define WO_WCL  35840
#define WO_WM2H 53248
#define WO_WM2L 70656

// ================= weight fuse kernels =================
__global__ void fuse_wab(const float* __restrict__ Wn2, const float* __restrict__ Wm1,
                         float* __restrict__ Wab) {
    int idx = blockIdx.x * 256 + threadIdx.x;
    int k = idx >> 8, j = idx & 255;
    const float* wm = (j < 128) ? (Wm1 + j) : (Wm1 + 128 * 128 + (j - 128));
    float acc = 0.f;
    #pragma unroll 4
    for (int t = 0; t < 128; t++) acc += Wn2[k * 128 + t] * wm[t * 128];
    Wab[idx] = acc;
}

__global__ void fuse_wc(const float* __restrict__ We2, const float* __restrict__ Wm1,
                        float* __restrict__ Wc) {
    int idx = blockIdx.x * 256 + threadIdx.x;
    int k = idx >> 7, j = idx & 127;
    float acc = 0.f;
    #pragma unroll 4
    for (int t = 0; t < 64; t++) acc += We2[k * 64 + t] * Wm1[(256 + t) * 128 + j];
    Wc[idx] = acc;
}

// parallel fuse_bias: one warp per output j (128 warps over 16 blocks)
__global__ void fuse_bias2(const float* __restrict__ bn2, const float* __restrict__ be2,
                           const float* __restrict__ bm1, const float* __restrict__ Wm1,
                           float* __restrict__ bc) {
    int lane = threadIdx.x & 31;
    int j = blockIdx.x * 8 + (threadIdx.x >> 5);
    if (j >= 128) return;
    float acc = 0.f;
    #pragma unroll
    for (int k = lane; k < 128; k += 32)
        acc += bn2[k] * (Wm1[k * 128 + j] + Wm1[(128 + k) * 128 + j]);
    #pragma unroll
    for (int t = lane; t < 64; t += 32)
        acc += be2[t] * Wm1[(256 + t) * 128 + j];
    #pragma unroll
    for (int o = 16; o; o >>= 1) acc += __shfl_xor_sync(0xffffffffu, acc, o);
    if (lane == 0) bc[j] = bm1[j] + acc;
}

// ================= bf16 hi/lo transposed weight prep (row-padded) =================
// edge: We1T pitch 72
__global__ void prep_we1t(const float* __restrict__ We1, __nv_bfloat16* __restrict__ hi,
                          __nv_bfloat16* __restrict__ lo) {
    int idx = blockIdx.x * 256 + threadIdx.x;   // 8192
    int n = idx >> 6, k = idx & 63;
    float w = We1[k * 128 + n];
    __nv_bfloat16 h = __float2bfloat16(w);
    float r = w - __bfloat162float(h);
    hi[n * 72 + k] = h;
    lo[n * 72 + k] = __float2bfloat16(r);
}

// edge: 128x128 transposed pitch 136
__global__ void prep_w128t(const float* __restrict__ W, __nv_bfloat16* __restrict__ hi,
                           __nv_bfloat16* __restrict__ lo) {
    int idx = blockIdx.x * 256 + threadIdx.x;   // 16384
    int n = idx >> 7, k = idx & 127;
    float w = W[k * 128 + n];
    __nv_bfloat16 h = __float2bfloat16(w);
    float r = w - __bfloat162float(h);
    hi[n * 136 + k] = h;
    lo[n * 136 + k] = __float2bfloat16(r);
}

// node: generic W[K][Nf] -> hi/lo [Nf][KP]
__global__ void prep_nodeT(const float* __restrict__ W, __nv_bfloat16* __restrict__ hi,
                           __nv_bfloat16* __restrict__ lo, int K, int Nf, int KP) {
    int idx = blockIdx.x * 256 + threadIdx.x;
    if (idx >= K * Nf) return;
    int n = idx % Nf;
    int k = idx / Nf;
    float w = W[idx];
    __nv_bfloat16 h = __float2bfloat16(w);
    float r = w - __bfloat162float(h);
    hi[n * KP + k] = h;
    lo[n * KP + k] = __float2bfloat16(r);
}

// ================= degree =================
__global__ void deg_kernel(const int* __restrict__ dst, float* __restrict__ deg, int E) {
    int e = blockIdx.x * blockDim.x + threadIdx.x;
    if (e < E) atomicAdd(&deg[dst[e]], 1.f);
}

// ================= tensor-core node GEMM =================
// C[M,Nfull] tile: 256 rows/block (16 warps x 16), NT=NB*8 cols via blockIdx.y
template<int KCH, int NB, bool RELU>
__global__ __launch_bounds__(512) void ngemm(
    const float* __restrict__ A, const uint4* __restrict__ Wt,
    const float* __restrict__ bias, float* __restrict__ C, int M, int Nfull)
{
    constexpr int K = KCH * 16;
    constexpr int KP = K + 8;
    constexpr int NT = NB * 8;
    extern __shared__ char nsm[];
    __nv_bfloat16* Whs = (__nv_bfloat16*)nsm;
    __nv_bfloat16* Wls = Whs + NT * KP;
    float* bs = (float*)(Wls + NT * KP);

    int tid = threadIdx.x;
    int n0 = blockIdx.y * NT;
    {
        const uint4* hsrc = Wt + n0 * KP / 8;
        const uint4* lsrc = Wt + (Nfull * KP) / 8 + n0 * KP / 8;
        uint4* hdst = (uint4*)Whs;
        uint4* ldst = (uint4*)Wls;
        constexpr int CNT = NT * KP / 8;
        for (int i = tid; i < CNT; i += 512) { hdst[i] = hsrc[i]; ldst[i] = lsrc[i]; }
        if (tid < NT) bs[tid] = bias ? bias[n0 + tid] : 0.f;
    }
    __syncthreads();

    int lane = tid & 31, wid = tid >> 5;
    int qr = lane >> 2, qc = (lane & 3) * 2;
    int m0 = (blockIdx.x * 16 + wid) * 16;
    int r0 = m0 + qr, r1 = r0 + 8;
    bool v0 = r0 < M, v1 = r1 < M;
    const float* a0 = A + (size_t)(v0 ? r0 : 0) * K;
    const float* a1 = A + (size_t)(v1 ? r1 : 0) * K;

    float acc[NB][4];
    #pragma unroll
    for (int nb = 0; nb < NB; nb++) {
        acc[nb][0] = acc[nb][1] = acc[nb][2] = acc[nb][3] = 0.f;
    }

    #pragma unroll
    for (int j = 0; j < KCH; j++) {
        uint32_t Ah[4], Al[4];
        float2 x0 = *(const float2*)(a0 + 16 * j + qc);
        float2 x1 = *(const float2*)(a1 + 16 * j + qc);
        float2 x2 = *(const float2*)(a0 + 16 * j + qc + 8);
        float2 x3 = *(const float2*)(a1 + 16 * j + qc + 8);
        pack_hl(x0.x, x0.y, Ah[0], Al[0]);
        pack_hl(x1.x, x1.y, Ah[1], Al[1]);
        pack_hl(x2.x, x2.y, Ah[2], Al[2]);
        pack_hl(x3.x, x3.y, Ah[3], Al[3]);
        #pragma unroll
        for (int nb = 0; nb < NB; nb++) {
            const __nv_bfloat16* ph = Whs + (8 * nb + qr) * KP + 16 * j + qc;
            const __nv_bfloat16* pl = Wls + (8 * nb + qr) * KP + 16 * j + qc;
            uint32_t bh0 = *(const uint32_t*)ph;
            uint32_t bh1 = *(const uint32_t*)(ph + 8);
            uint32_t bl0 = *(const uint32_t*)pl;
            uint32_t bl1 = *(const uint32_t*)(pl + 8);
            mma_bf16(acc[nb], Ah, bh0, bh1);
            mma_bf16(acc[nb], Ah, bl0, bl1);
            mma_bf16(acc[nb], Al, bh0, bh1);
        }
    }

    #pragma unroll
    for (int nb = 0; nb < NB; nb++) {
        int col = 8 * nb + qc;
        float b0v = bs[col], b1v = bs[col + 1];
        float u0 = acc[nb][0] + b0v, u1 = acc[nb][1] + b1v;
        float u2 = acc[nb][2] + b0v, u3 = acc[nb][3] + b1v;
        if (RELU) {
            u0 = fmaxf(u0, 0.f); u1 = fmaxf(u1, 0.f);
            u2 = fmaxf(u2, 0.f); u3 = fmaxf(u3, 0.f);
        }
        if (v0) *(float2*)(C + (size_t)r0 * Nfull + n0 + col) = make_float2(u0, u1);
        if (v1) *(float2*)(C + (size_t)r1 * Nfull + n0 + col) = make_float2(u2, u3);
    }
}

// ================= mma.sync fused edge kernel (unchanged from R3) =================
#define EDGE3_SMEM (176128 + 1024)

template<int NC>
__device__ __forceinline__ void stage_mma(
    float acc[16][4], const uint32_t Ah[8][4], const uint32_t Al[8][4],
    const __nv_bfloat16* __restrict__ Wh, const __nv_bfloat16* __restrict__ Wl,
    int KP, int qr, int qc)
{
    #pragma unroll
    for (int j = 0; j < NC; j++) {
        #pragma unroll
        for (int nb = 0; nb < 16; nb++) {
            const __nv_bfloat16* ph = Wh + (8 * nb + qr) * KP + 16 * j + qc;
            const __nv_bfloat16* pl = Wl + (8 * nb + qr) * KP + 16 * j + qc;
            uint32_t bh0 = *(const uint32_t*)ph;
            uint32_t bh1 = *(const uint32_t*)(ph + 8);
            uint32_t bl0 = *(const uint32_t*)pl;
            uint32_t bl1 = *(const uint32_t*)(pl + 8);
            mma_bf16(acc[nb], Ah[j], bh0, bh1);
            mma_bf16(acc[nb], Ah[j], bl0, bl1);
            mma_bf16(acc[nb], Al[j], bh0, bh1);
        }
    }
}

__global__ __launch_bounds__(256) void edge_kernel3(
    const float* __restrict__ ea,
    const int* __restrict__ src, const int* __restrict__ dst,
    const uint4* __restrict__ wpack,
    const float* __restrict__ be1, const float* __restrict__ bc,
    const float* __restrict__ ab, float* __restrict__ agg, int E)
{
    extern __shared__ char smem[];
    __nv_bfloat16* W = (__nv_bfloat16*)smem;
    float* be1s = (float*)(smem + 176128);
    float* bcs  = (float*)(smem + 176128 + 512);

    int tid = threadIdx.x;
    {
        uint4* s4 = (uint4*)smem;
        for (int i = tid; i < 11008; i += 256) s4[i] = wpack[i];
        if (tid < 128) { be1s[tid] = be1[tid]; bcs[tid] = bc[tid]; }
    }
    __syncthreads();

    const __nv_bfloat16* We1h = W + WO_WE1H;
    const __nv_bfloat16* We1l = W + WO_WE1L;
    const __nv_bfloat16* Wch  = W + WO_WCH;
    const __nv_bfloat16* Wcl  = W + WO_WCL;
    const __nv_bfloat16* Wm2h = W + WO_WM2H;
    const __nv_bfloat16* Wm2l = W + WO_WM2L;

    int lane = tid & 31, wid = tid >> 5;
    int qr = lane >> 2;
    int qc = (lane & 3) * 2;

    int nG = (E + 15) >> 4;
    for (int g = blockIdx.x * 8 + wid; g < nG; g += gridDim.x * 8) {
        int e0 = g << 4;
        int er0 = e0 + qr, er1 = er0 + 8;
        bool v0 = er0 < E, v1 = er1 < E;
        int ec0 = v0 ? er0 : 0, ec1 = v1 ? er1 : 0;
        int d0 = dst[ec0], d1 = dst[ec1];
        int s0 = src[ec0], s1 = src[ec1];

        uint32_t Ah[8][4], Al[8][4];
        float acc[16][4];

        #pragma unroll
        for (int j = 0; j < 4; j++) {
            const float* r0p = ea + (size_t)ec0 * 64 + 16 * j + qc;
            const float* r1p = ea + (size_t)ec1 * 64 + 16 * j + qc;
            float2 x0 = *(const float2*)r0p;
            float2 x1 = *(const float2*)r1p;
            float2 x2 = *(const float2*)(r0p + 8);
            float2 x3 = *(const float2*)(r1p + 8);
            pack_hl(x0.x, x0.y, Ah[j][0], Al[j][0]);
            pack_hl(x1.x, x1.y, Ah[j][1], Al[j][1]);
            pack_hl(x2.x, x2.y, Ah[j][2], Al[j][2]);
            pack_hl(x3.x, x3.y, Ah[j][3], Al[j][3]);
        }

        // S1
        #pragma unroll
        for (int nb = 0; nb < 16; nb++)
            #pragma unroll
            for (int q = 0; q < 4; q++) acc[nb][q] = 0.f;
        stage_mma<4>(acc, Ah, Al, We1h, We1l, 72, qr, qc);
        #pragma unroll
        for (int nb = 0; nb < 16; nb++) {
            int col = 8 * nb + qc;
            float b0 = be1s[col], b1 = be1s[col + 1];
            float u0 = fmaxf(acc[nb][0] + b0, 0.f);
            float u1 = fmaxf(acc[nb][1] + b1, 0.f);
            float u2 = fmaxf(acc[nb][2] + b0, 0.f);
            float u3 = fmaxf(acc[nb][3] + b1, 0.f);
            int j = nb >> 1, q = (nb & 1) * 2;
            pack_hl(u0, u1, Ah[j][q],     Al[j][q]);
            pack_hl(u2, u3, Ah[j][q + 1], Al[j][q + 1]);
        }

        // S2
        #pragma unroll
        for (int nb = 0; nb < 16; nb++)
            #pragma unroll
            for (int q = 0; q < 4; q++) acc[nb][q] = 0.f;
        stage_mma<8>(acc, Ah, Al, Wch, Wcl, 136, qr, qc);
        {
            const float* a0p = ab + (size_t)d0 * 256;
            const float* a1p = ab + (size_t)d1 * 256;
            const float* b0p = ab + (size_t)s0 * 256 + 128;
            const float* b1p = ab + (size_t)s1 * 256 + 128;
            #pragma unroll
            for (int nb = 0; nb < 16; nb++) {
                int col = 8 * nb + qc;
                float2 ga0 = *(const float2*)(a0p + col);
                float2 ga1 = *(const float2*)(a1p + col);
                float2 gb0 = *(const float2*)(b0p + col);
                float2 gb1 = *(const float2*)(b1p + col);
                float bc0 = bcs[col], bc1 = bcs[col + 1];
                float u0 = fmaxf(acc[nb][0] + ga0.x + gb0.x + bc0, 0.f);
                float u1 = fmaxf(acc[nb][1] + ga0.y + gb0.y + bc1, 0.f);
                float u2 = fmaxf(acc[nb][2] + ga1.x + gb1.x + bc0, 0.f);
                float u3 = fmaxf(acc[nb][3] + ga1.y + gb1.y + bc1, 0.f);
                int j = nb >> 1, q = (nb & 1) * 2;
                pack_hl(u0, u1, Ah[j][q],     Al[j][q]);
                pack_hl(u2, u3, Ah[j][q + 1], Al[j][q + 1]);
            }
        }

        // S3
        #pragma unroll
        for (int nb = 0; nb < 16; nb++)
            #pragma unroll
            for (int q = 0; q < 4; q++) acc[nb][q] = 0.f;
        stage_mma<8>(acc, Ah, Al, Wm2h, Wm2l, 136, qr, qc);
        {
            float* g0 = agg + (size_t)d0 * 128;
            float* g1 = agg + (size_t)d1 * 128;
            #pragma unroll
            for (int nb = 0; nb < 16; nb++) {
                int col = 8 * nb + qc;
                if (v0)
                    asm volatile("red.global.add.v2.f32 [%0], {%1, %2};"
                                 :: "l"(g0 + col), "f"(acc[nb][0]), "f"(acc[nb][1]) : "memory");
                if (v1)
                    asm volatile("red.global.add.v2.f32 [%0], {%1, %2};"
                                 :: "l"(g1 + col), "f"(acc[nb][2]), "f"(acc[nb][3]) : "memory");
            }
        }
    }
}

// ================= LayerNorm + relu =================
__global__ void ln_kernel(const float* __restrict__ agg, const float* __restrict__ deg,
                          const float* __restrict__ bm2, const float* __restrict__ lnw,
                          const float* __restrict__ lnb, float* __restrict__ xout, int N)
{
    int gwarp = (blockIdx.x * blockDim.x + threadIdx.x) >> 5;
    int lane = threadIdx.x & 31;
    if (gwarp >= N) return;
    float d = deg[gwarp];
    float inv = 1.f / fmaxf(d, 1.f);
    float add = (d > 0.f) ? 1.f : 0.f;
    float4 v = ((const float4*)agg)[(size_t)gwarp * 32 + lane];
    float4 b = ((const float4*)bm2)[lane];
    v.x = v.x * inv + add * b.x;
    v.y = v.y * inv + add * b.y;
    v.z = v.z * inv + add * b.z;
    v.w = v.w * inv + add * b.w;
    float s = v.x + v.y + v.z + v.w;
    #pragma unroll
    for (int o = 16; o; o >>= 1) s += __shfl_xor_sync(0xffffffffu, s, o);
    float mu = s * (1.f / 128.f);
    float d0 = v.x - mu, d1 = v.y - mu, d2 = v.z - mu, d3 = v.w - mu;
    float q = d0 * d0 + d1 * d1 + d2 * d2 + d3 * d3;
    #pragma unroll
    for (int o = 16; o; o >>= 1) q += __shfl_xor_sync(0xffffffffu, q, o);
    float rs = rsqrtf(q * (1.f / 128.f) + 1e-5f);
    float4 w = ((const float4*)lnw)[lane];
    float4 bb = ((const float4*)lnb)[lane];
    float4 o;
    o.x = fmaxf(d0 * rs * w.x + bb.x, 0.f);
    o.y = fmaxf(d1 * rs * w.y + bb.y, 0.f);
    o.z = fmaxf(d2 * rs * w.z + bb.z, 0.f);
    o.w = fmaxf(d3 * rs * w.w + bb.w, 0.f);
    ((float4*)xout)[(size_t)gwarp * 32 + lane] = o;
}

// ================= host =================
extern "C" void kernel_launch(void* const* d_in, const int* in_sizes, int n_in,
                              void* d_out, int out_size)
{
    const float* x    = (const float*)d_in[0];
    const float* ea   = (const float*)d_in[1];
    const int*   eidx = (const int*)  d_in[2];
    const float* Wn1  = (const float*)d_in[3];
    const float* bn1  = (const float*)d_in[4];
    const float* Wn2  = (const float*)d_in[5];
    const float* bn2  = (const float*)d_in[6];
    const float* We1  = (const float*)d_in[7];
    const float* be1  = (const float*)d_in[8];
    const float* We2  = (const float*)d_in[9];
    const float* be2  = (const float*)d_in[10];
    const float* Wm1  = (const float*)d_in[11];
    const float* bm1  = (const float*)d_in[12];
    const float* Wm2  = (const float*)d_in[13];
    const float* bm2  = (const float*)d_in[14];
    const float* lnw  = (const float*)d_in[15];
    const float* lnb  = (const float*)d_in[16];
    const float* Wf   = (const float*)d_in[17];
    const float* bf   = (const float*)d_in[18];

    int N = in_sizes[0] / 128;
    int E = in_sizes[1] / 64;
    const int* srcp = eidx;
    const int* dstp = eidx + E;

    float *h1n, *ab, *xb, *agg, *deg, *Wab, *Wc, *bc;
    uint4 *wpack, *wnode, *wf;
    cudaGetSymbolAddress((void**)&h1n, g_h1n);
    cudaGetSymbolAddress((void**)&ab,  g_ab);
    cudaGetSymbolAddress((void**)&xb,  g_x);
    cudaGetSymbolAddress((void**)&agg, g_agg);
    cudaGetSymbolAddress((void**)&deg, g_deg);
    cudaGetSymbolAddress((void**)&Wab, g_Wab);
    cudaGetSymbolAddress((void**)&Wc,  g_Wc);
    cudaGetSymbolAddress((void**)&bc,  g_bc);
    cudaGetSymbolAddress((void**)&wpack, g_wpack);
    cudaGetSymbolAddress((void**)&wnode, g_wnode);
    cudaGetSymbolAddress((void**)&wf, g_wf);
    __nv_bfloat16* wb = (__nv_bfloat16*)wpack;
    __nv_bfloat16* nb = (__nv_bfloat16*)wnode;
    __nv_bfloat16* wfb = (__nv_bfloat16*)wf;

    cudaFuncSetAttribute(edge_kernel3, cudaFuncAttributeMaxDynamicSharedMemorySize,
                         EDGE3_SMEM);
    int smW1  = 2 * 128 * 136 * 2 + 512;   // ngemm<8,16>
    int smWab = 2 * 128 * 264 * 2 + 512;   // ngemm<16,16>
    int smWf  = 2 * 64 * 136 * 2 + 256;    // ngemm<8,8>
    cudaFuncSetAttribute(ngemm<8, 16, true>,  cudaFuncAttributeMaxDynamicSharedMemorySize, smW1);
    cudaFuncSetAttribute(ngemm<16, 16, false>, cudaFuncAttributeMaxDynamicSharedMemorySize, smWab);
    cudaFuncSetAttribute(ngemm<8, 8, false>,  cudaFuncAttributeMaxDynamicSharedMemorySize, smWf);

    cudaMemsetAsync(deg, 0, (size_t)N * sizeof(float));
    deg_kernel<<<(E + 255) / 256, 256>>>(dstp, deg, E);

    for (int l = 0; l < LLAYERS; l++) {
        fuse_wab<<<256, 256>>>(Wn2 + (size_t)l * 256 * 128, Wm1 + (size_t)l * 320 * 128,
                               Wab + (size_t)l * 256 * 256);
        fuse_wc<<<64, 256>>>(We2 + (size_t)l * 128 * 64, Wm1 + (size_t)l * 320 * 128,
                             Wc + (size_t)l * 128 * 128);
        fuse_bias2<<<16, 256>>>(bn2 + l * 128, be2 + l * 64, bm1 + l * 128,
                                Wm1 + (size_t)l * 320 * 128, bc + l * 128);
        __nv_bfloat16* base = wb + (size_t)l * WP_LAYER_ELEMS;
        prep_we1t<<<32, 256>>>(We1 + (size_t)l * 64 * 128,
                               base + WO_WE1H, base + WO_WE1L);
        prep_w128t<<<64, 256>>>(Wc + (size_t)l * 128 * 128,
                                base + WO_WCH, base + WO_WCL);
        prep_w128t<<<64, 256>>>(Wm2 + (size_t)l * 128 * 128,
                                base + WO_WM2H, base + WO_WM2L);
        // node weights
        __nv_bfloat16* npb = nb + (size_t)l * NP_LAYER_ELEMS;
        prep_nodeT<<<(128 * 256 + 255) / 256, 256>>>(
            Wn1 + (size_t)l * 128 * 256, npb + NP_W1, npb + NP_W1 + 256 * 136,
            128, 256, 136);
        prep_nodeT<<<(256 * 256 + 255) / 256, 256>>>(
            Wab + (size_t)l * 256 * 256, npb + NP_WAB, npb + NP_WAB + 256 * 264,
            256, 256, 264);
    }
    prep_nodeT<<<(128 * 64 + 255) / 256, 256>>>(Wf, wfb, wfb + 64 * 136, 128, 64, 136);

    const float* curx = x;
    int gRows = (N + 255) / 256;
    for (int l = 0; l < LLAYERS; l++) {
        __nv_bfloat16* npb = nb + (size_t)l * NP_LAYER_ELEMS;
        ngemm<8, 16, true><<<dim3(gRows, 2), 512, smW1>>>(
            curx, (const uint4*)(npb + NP_W1), bn1 + l * 256, h1n, N, 256);
        ngemm<16, 16, false><<<dim3(gRows, 2), 512, smWab>>>(
            h1n, (const uint4*)(npb + NP_WAB), (const float*)nullptr, ab, N, 256);
        cudaMemsetAsync(agg, 0, (size_t)N * 128 * sizeof(float));
        edge_kernel3<<<148, 256, EDGE3_SMEM>>>(
            ea, srcp, dstp,
            (const uint4*)(wb + (size_t)l * WP_LAYER_ELEMS),
            be1 + l * 128, bc + l * 128, ab, agg, E);
        ln_kernel<<<(N + 7) / 8, 256>>>(agg, deg, bm2 + l * 128, lnw + l * 128,
                                        lnb + l * 128, xb, N);
        curx = xb;
    }
    ngemm<8, 8, false><<<dim3(gRows, 1), 512, smWf>>>(
        curx, (const uint4*)wfb, bf, (float*)d_out, N, 64);
}

// round 5
// speedup vs baseline: 3.9347x; 1.0293x over previous
#include <cuda_runtime.h>
#include <cuda_bf16.h>
#include <cstdint>

#define MAXN 50000
#define MAXE 800000
#define LLAYERS 3

// ================= helpers =================
__device__ __forceinline__ uint32_t packbf(float lo_v, float hi_v) {
    uint32_t r;
    asm("cvt.rn.satfinite.bf16x2.f32 %0, %1, %2;" : "=r"(r) : "f"(hi_v), "f"(lo_v));
    return r;
}
__device__ __forceinline__ float bfl(uint32_t p) { return __uint_as_float(p << 16); }
__device__ __forceinline__ float bfh(uint32_t p) { return __uint_as_float(p & 0xffff0000u); }

__device__ __forceinline__ void pack_hl(float v0, float v1, uint32_t& h, uint32_t& l) {
    h = packbf(v0, v1);
    l = packbf(v0 - bfl(h), v1 - bfh(h));
}

__device__ __forceinline__ void mma_bf16(float* c, const uint32_t* a, uint32_t b0, uint32_t b1) {
    asm volatile(
        "mma.sync.aligned.m16n8k16.row.col.f32.bf16.bf16.f32 "
        "{%0,%1,%2,%3}, {%4,%5,%6,%7}, {%8,%9}, {%0,%1,%2,%3};\n"
        : "+f"(c[0]), "+f"(c[1]), "+f"(c[2]), "+f"(c[3])
        : "r"(a[0]), "r"(a[1]), "r"(a[2]), "r"(a[3]), "r"(b0), "r"(b1));
}

// ================= scratch (static device globals) =================
__device__ float g_h1n[MAXN * 256];
__device__ float g_ab [MAXN * 256];
__device__ float g_x  [MAXN * 128];
__device__ float g_agg[MAXN * 128];
__device__ float g_deg[MAXN];
__device__ float g_Wab [LLAYERS * 256 * 256];
__device__ float g_Wc  [LLAYERS * 128 * 128];
__device__ float g_bc  [LLAYERS * 128];
// per-layer packed bf16 transposed edge weights, 88064 elems / layer
#define WP_LAYER_ELEMS 88064
__device__ uint4 g_wpack[LLAYERS * WP_LAYER_ELEMS * 2 / 16];
// per-layer node weights: [W1hi 256x136][W1lo][WABhi 256x264][WABlo]
#define NP_LAYER_ELEMS 204800
#define NP_W1  0
#define NP_WAB 69632
__device__ uint4 g_wnode[LLAYERS * NP_LAYER_ELEMS * 2 / 16];
__device__ uint4 g_wf[2 * 64 * 136 * 2 / 16];

#define WO_WE1H 0
#define WO_WE1L 9216
#define WO_WCH  18432
#define WO_WCL  35840
#define WO_WM2H 53248
#define WO_WM2L 70656

// ================= fused weight-fuse kernel =================
// blocks [0,768): Wab ; [768,960): Wc ; [960,1008): bc
__global__ __launch_bounds__(256) void fuse_all(
    const float* __restrict__ Wn2, const float* __restrict__ Wm1,
    const float* __restrict__ We2, const float* __restrict__ bn2,
    const float* __restrict__ be2, const float* __restrict__ bm1,
    float* __restrict__ Wab, float* __restrict__ Wc, float* __restrict__ bc)
{
    int b = blockIdx.x, tid = threadIdx.x;
    if (b < 768) {
        int l = b >> 8;
        int idx = (b & 255) * 256 + tid;            // 0..65535
        const float* wn2 = Wn2 + (size_t)l * 256 * 128;
        const float* wm1 = Wm1 + (size_t)l * 320 * 128;
        int k = idx >> 8, j = idx & 255;
        const float* wm = (j < 128) ? (wm1 + j) : (wm1 + 128 * 128 + (j - 128));
        float acc = 0.f;
        #pragma unroll 4
        for (int t = 0; t < 128; t++) acc += wn2[k * 128 + t] * wm[t * 128];
        Wab[(size_t)l * 65536 + idx] = acc;
    } else if (b < 960) {
        int lb = b - 768;
        int l = lb / 64;
        int idx = (lb % 64) * 256 + tid;            // 0..16383
        const float* we2 = We2 + (size_t)l * 128 * 64;
        const float* wm1 = Wm1 + (size_t)l * 320 * 128;
        int k = idx >> 7, j = idx & 127;
        float acc = 0.f;
        #pragma unroll 4
        for (int t = 0; t < 64; t++) acc += we2[k * 64 + t] * wm1[(256 + t) * 128 + j];
        Wc[(size_t)l * 16384 + idx] = acc;
    } else {
        int lb = b - 960;
        int l = lb / 16;
        int lane = tid & 31;
        int j = (lb % 16) * 8 + (tid >> 5);
        const float* wm1 = Wm1 + (size_t)l * 320 * 128;
        const float* bn2l = bn2 + l * 128;
        const float* be2l = be2 + l * 64;
        float acc = 0.f;
        #pragma unroll
        for (int k = lane; k < 128; k += 32)
            acc += bn2l[k] * (wm1[k * 128 + j] + wm1[(128 + k) * 128 + j]);
        #pragma unroll
        for (int t = lane; t < 64; t += 32)
            acc += be2l[t] * wm1[(256 + t) * 128 + j];
        #pragma unroll
        for (int o = 16; o; o >>= 1) acc += __shfl_xor_sync(0xffffffffu, acc, o);
        if (lane == 0) bc[l * 128 + j] = bm1[l * 128 + j] + acc;
    }
}

// ================= fused bf16 hi/lo transpose prep kernel =================
__device__ __forceinline__ void splitw(float w, __nv_bfloat16* hi, __nv_bfloat16* lo, int o) {
    __nv_bfloat16 h = __float2bfloat16(w);
    hi[o] = h;
    lo[o] = __float2bfloat16(w - __bfloat162float(h));
}

// blocks: [0,96) we1t | [96,288) WcT | [288,480) Wm2T | [480,864) W1 | [864,1632) WAB | [1632,1664) Wf
__global__ __launch_bounds__(256) void prep_all(
    const float* __restrict__ We1, const float* __restrict__ WcG,
    const float* __restrict__ Wm2, const float* __restrict__ Wn1,
    const float* __restrict__ WabG, const float* __restrict__ Wf,
    __nv_bfloat16* __restrict__ wb, __nv_bfloat16* __restrict__ nbw,
    __nv_bfloat16* __restrict__ wfb)
{
    int b = blockIdx.x, tid = threadIdx.x;
    if (b < 96) {
        int l = b / 32;
        int idx = (b % 32) * 256 + tid;             // 8192
        int n = idx >> 6, k = idx & 63;
        float w = We1[(size_t)l * 8192 + k * 128 + n];
        __nv_bfloat16* base = wb + (size_t)l * WP_LAYER_ELEMS;
        splitw(w, base + WO_WE1H, base + WO_WE1L, n * 72 + k);
    } else if (b < 288) {
        int lb = b - 96;
        int l = lb / 64;
        int idx = (lb % 64) * 256 + tid;            // 16384
        int n = idx >> 7, k = idx & 127;
        float w = WcG[(size_t)l * 16384 + k * 128 + n];
        __nv_bfloat16* base = wb + (size_t)l * WP_LAYER_ELEMS;
        splitw(w, base + WO_WCH, base + WO_WCL, n * 136 + k);
    } else if (b < 480) {
        int lb = b - 288;
        int l = lb / 64;
        int idx = (lb % 64) * 256 + tid;            // 16384
        int n = idx >> 7, k = idx & 127;
        float w = Wm2[(size_t)l * 16384 + k * 128 + n];
        __nv_bfloat16* base = wb + (size_t)l * WP_LAYER_ELEMS;
        splitw(w, base + WO_WM2H, base + WO_WM2L, n * 136 + k);
    } else if (b < 864) {
        int lb = b - 480;
        int l = lb / 128;
        int idx = (lb % 128) * 256 + tid;           // 32768 ; K=128,Nf=256,KP=136
        int n = idx & 255, k = idx >> 8;
        float w = Wn1[(size_t)l * 32768 + idx];
        __nv_bfloat16* base = nbw + (size_t)l * NP_LAYER_ELEMS + NP_W1;
        splitw(w, base, base + 256 * 136, n * 136 + k);
    } else if (b < 1632) {
        int lb = b - 864;
        int l = lb / 256;
        int idx = (lb % 256) * 256 + tid;           // 65536 ; K=256,Nf=256,KP=264
        int n = idx & 255, k = idx >> 8;
        float w = WabG[(size_t)l * 65536 + idx];
        __nv_bfloat16* base = nbw + (size_t)l * NP_LAYER_ELEMS + NP_WAB;
        splitw(w, base, base + 256 * 264, n * 264 + k);
    } else {
        int idx = (b - 1632) * 256 + tid;           // 8192 ; K=128,Nf=64,KP=136
        int n = idx & 63, k = idx >> 6;
        splitw(Wf[idx], wfb, wfb + 64 * 136, n * 136 + k);
    }
}

// ================= init (zero agg + deg) + degree =================
__global__ void zero_init(float* __restrict__ agg, float* __restrict__ deg, int N) {
    int i = blockIdx.x * blockDim.x + threadIdx.x;
    if (i < N * 32) ((float4*)agg)[i] = make_float4(0.f, 0.f, 0.f, 0.f);
    if (i < N) deg[i] = 0.f;
}

__global__ void deg_kernel(const int* __restrict__ dst, float* __restrict__ deg, int E) {
    int e = blockIdx.x * blockDim.x + threadIdx.x;
    if (e < E) atomicAdd(&deg[dst[e]], 1.f);
}

// ================= tensor-core node GEMM (256 thr, partial unroll) =================
template<int KCH, int NB, bool RELU>
__global__ __launch_bounds__(256) void ngemm(
    const float* __restrict__ A, const uint4* __restrict__ Wt,
    const float* __restrict__ bias, float* __restrict__ C, int M, int Nfull)
{
    constexpr int K = KCH * 16;
    constexpr int KP = K + 8;
    constexpr int NT = NB * 8;
    extern __shared__ char nsm[];
    __nv_bfloat16* Whs = (__nv_bfloat16*)nsm;
    __nv_bfloat16* Wls = Whs + NT * KP;
    float* bs = (float*)(Wls + NT * KP);

    int tid = threadIdx.x;
    int n0 = blockIdx.y * NT;
    {
        const uint4* hsrc = Wt + n0 * KP / 8;
        const uint4* lsrc = Wt + (Nfull * KP) / 8 + n0 * KP / 8;
        uint4* hdst = (uint4*)Whs;
        uint4* ldst = (uint4*)Wls;
        constexpr int CNT = NT * KP / 8;
        for (int i = tid; i < CNT; i += 256) { hdst[i] = hsrc[i]; ldst[i] = lsrc[i]; }
        if (tid < NT) bs[tid] = bias ? bias[n0 + tid] : 0.f;
    }
    __syncthreads();

    int lane = tid & 31, wid = tid >> 5;
    int qr = lane >> 2, qc = (lane & 3) * 2;
    int m0 = (blockIdx.x * 8 + wid) * 16;
    int r0 = m0 + qr, r1 = r0 + 8;
    bool v0 = r0 < M, v1 = r1 < M;
    const float* a0 = A + (size_t)(v0 ? r0 : 0) * K;
    const float* a1 = A + (size_t)(v1 ? r1 : 0) * K;

    float acc[NB][4];
    #pragma unroll
    for (int nb = 0; nb < NB; nb++) {
        acc[nb][0] = acc[nb][1] = acc[nb][2] = acc[nb][3] = 0.f;
    }

    #pragma unroll 2
    for (int j = 0; j < KCH; j++) {
        uint32_t Ah[4], Al[4];
        float2 x0 = *(const float2*)(a0 + 16 * j + qc);
        float2 x1 = *(const float2*)(a1 + 16 * j + qc);
        float2 x2 = *(const float2*)(a0 + 16 * j + qc + 8);
        float2 x3 = *(const float2*)(a1 + 16 * j + qc + 8);
        pack_hl(x0.x, x0.y, Ah[0], Al[0]);
        pack_hl(x1.x, x1.y, Ah[1], Al[1]);
        pack_hl(x2.x, x2.y, Ah[2], Al[2]);
        pack_hl(x3.x, x3.y, Ah[3], Al[3]);
        #pragma unroll
        for (int nb = 0; nb < NB; nb++) {
            const __nv_bfloat16* ph = Whs + (8 * nb + qr) * KP + 16 * j + qc;
            const __nv_bfloat16* pl = Wls + (8 * nb + qr) * KP + 16 * j + qc;
            uint32_t bh0 = *(const uint32_t*)ph;
            uint32_t bh1 = *(const uint32_t*)(ph + 8);
            uint32_t bl0 = *(const uint32_t*)pl;
            uint32_t bl1 = *(const uint32_t*)(pl + 8);
            mma_bf16(acc[nb], Ah, bh0, bh1);
            mma_bf16(acc[nb], Ah, bl0, bl1);
            mma_bf16(acc[nb], Al, bh0, bh1);
        }
    }

    #pragma unroll
    for (int nb = 0; nb < NB; nb++) {
        int col = 8 * nb + qc;
        float b0v = bs[col], b1v = bs[col + 1];
        float u0 = acc[nb][0] + b0v, u1 = acc[nb][1] + b1v;
        float u2 = acc[nb][2] + b0v, u3 = acc[nb][3] + b1v;
        if (RELU) {
            u0 = fmaxf(u0, 0.f); u1 = fmaxf(u1, 0.f);
            u2 = fmaxf(u2, 0.f); u3 = fmaxf(u3, 0.f);
        }
        if (v0) *(float2*)(C + (size_t)r0 * Nfull + n0 + col) = make_float2(u0, u1);
        if (v1) *(float2*)(C + (size_t)r1 * Nfull + n0 + col) = make_float2(u2, u3);
    }
}

// ================= mma.sync fused edge kernel (unchanged from R3/R4) =================
#define EDGE3_SMEM (176128 + 1024)

template<int NC>
__device__ __forceinline__ void stage_mma(
    float acc[16][4], const uint32_t Ah[8][4], const uint32_t Al[8][4],
    const __nv_bfloat16* __restrict__ Wh, const __nv_bfloat16* __restrict__ Wl,
    int KP, int qr, int qc)
{
    #pragma unroll
    for (int j = 0; j < NC; j++) {
        #pragma unroll
        for (int nb = 0; nb < 16; nb++) {
            const __nv_bfloat16* ph = Wh + (8 * nb + qr) * KP + 16 * j + qc;
            const __nv_bfloat16* pl = Wl + (8 * nb + qr) * KP + 16 * j + qc;
            uint32_t bh0 = *(const uint32_t*)ph;
            uint32_t bh1 = *(const uint32_t*)(ph + 8);
            uint32_t bl0 = *(const uint32_t*)pl;
            uint32_t bl1 = *(const uint32_t*)(pl + 8);
            mma_bf16(acc[nb], Ah[j], bh0, bh1);
            mma_bf16(acc[nb], Ah[j], bl0, bl1);
            mma_bf16(acc[nb], Al[j], bh0, bh1);
        }
    }
}

__global__ __launch_bounds__(256) void edge_kernel3(
    const float* __restrict__ ea,
    const int* __restrict__ src, const int* __restrict__ dst,
    const uint4* __restrict__ wpack,
    const float* __restrict__ be1, const float* __restrict__ bc,
    const float* __restrict__ ab, float* __restrict__ agg, int E)
{
    extern __shared__ char smem[];
    __nv_bfloat16* W = (__nv_bfloat16*)smem;
    float* be1s = (float*)(smem + 176128);
    float* bcs  = (float*)(smem + 176128 + 512);

    int tid = threadIdx.x;
    {
        uint4* s4 = (uint4*)smem;
        for (int i = tid; i < 11008; i += 256) s4[i] = wpack[i];
        if (tid < 128) { be1s[tid] = be1[tid]; bcs[tid] = bc[tid]; }
    }
    __syncthreads();

    const __nv_bfloat16* We1h = W + WO_WE1H;
    const __nv_bfloat16* We1l = W + WO_WE1L;
    const __nv_bfloat16* Wch  = W + WO_WCH;
    const __nv_bfloat16* Wcl  = W + WO_WCL;
    const __nv_bfloat16* Wm2h = W + WO_WM2H;
    const __nv_bfloat16* Wm2l = W + WO_WM2L;

    int lane = tid & 31, wid = tid >> 5;
    int qr = lane >> 2;
    int qc = (lane & 3) * 2;

    int nG = (E + 15) >> 4;
    for (int g = blockIdx.x * 8 + wid; g < nG; g += gridDim.x * 8) {
        int e0 = g << 4;
        int er0 = e0 + qr, er1 = er0 + 8;
        bool v0 = er0 < E, v1 = er1 < E;
        int ec0 = v0 ? er0 : 0, ec1 = v1 ? er1 : 0;
        int d0 = dst[ec0], d1 = dst[ec1];
        int s0 = src[ec0], s1 = src[ec1];

        uint32_t Ah[8][4], Al[8][4];
        float acc[16][4];

        #pragma unroll
        for (int j = 0; j < 4; j++) {
            const float* r0p = ea + (size_t)ec0 * 64 + 16 * j + qc;
            const float* r1p = ea + (size_t)ec1 * 64 + 16 * j + qc;
            float2 x0 = *(const float2*)r0p;
            float2 x1 = *(const float2*)r1p;
            float2 x2 = *(const float2*)(r0p + 8);
            float2 x3 = *(const float2*)(r1p + 8);
            pack_hl(x0.x, x0.y, Ah[j][0], Al[j][0]);
            pack_hl(x1.x, x1.y, Ah[j][1], Al[j][1]);
            pack_hl(x2.x, x2.y, Ah[j][2], Al[j][2]);
            pack_hl(x3.x, x3.y, Ah[j][3], Al[j][3]);
        }

        // S1
        #pragma unroll
        for (int nb = 0; nb < 16; nb++)
            #pragma unroll
            for (int q = 0; q < 4; q++) acc[nb][q] = 0.f;
        stage_mma<4>(acc, Ah, Al, We1h, We1l, 72, qr, qc);
        #pragma unroll
        for (int nb = 0; nb < 16; nb++) {
            int col = 8 * nb + qc;
            float b0 = be1s[col], b1 = be1s[col + 1];
            float u0 = fmaxf(acc[nb][0] + b0, 0.f);
            float u1 = fmaxf(acc[nb][1] + b1, 0.f);
            float u2 = fmaxf(acc[nb][2] + b0, 0.f);
            float u3 = fmaxf(acc[nb][3] + b1, 0.f);
            int j = nb >> 1, q = (nb & 1) * 2;
            pack_hl(u0, u1, Ah[j][q],     Al[j][q]);
            pack_hl(u2, u3, Ah[j][q + 1], Al[j][q + 1]);
        }

        // S2
        #pragma unroll
        for (int nb = 0; nb < 16; nb++)
            #pragma unroll
            for (int q = 0; q < 4; q++) acc[nb][q] = 0.f;
        stage_mma<8>(acc, Ah, Al, Wch, Wcl, 136, qr, qc);
        {
            const float* a0p = ab + (size_t)d0 * 256;
            const float* a1p = ab + (size_t)d1 * 256;
            const float* b0p = ab + (size_t)s0 * 256 + 128;
            const float* b1p = ab + (size_t)s1 * 256 + 128;
            #pragma unroll
            for (int nb = 0; nb < 16; nb++) {
                int col = 8 * nb + qc;
                float2 ga0 = *(const float2*)(a0p + col);
                float2 ga1 = *(const float2*)(a1p + col);
                float2 gb0 = *(const float2*)(b0p + col);
                float2 gb1 = *(const float2*)(b1p + col);
                float bc0 = bcs[col], bc1 = bcs[col + 1];
                float u0 = fmaxf(acc[nb][0] + ga0.x + gb0.x + bc0, 0.f);
                float u1 = fmaxf(acc[nb][1] + ga0.y + gb0.y + bc1, 0.f);
                float u2 = fmaxf(acc[nb][2] + ga1.x + gb1.x + bc0, 0.f);
                float u3 = fmaxf(acc[nb][3] + ga1.y + gb1.y + bc1, 0.f);
                int j = nb >> 1, q = (nb & 1) * 2;
                pack_hl(u0, u1, Ah[j][q],     Al[j][q]);
                pack_hl(u2, u3, Ah[j][q + 1], Al[j][q + 1]);
            }
        }

        // S3
        #pragma unroll
        for (int nb = 0; nb < 16; nb++)
            #pragma unroll
            for (int q = 0; q < 4; q++) acc[nb][q] = 0.f;
        stage_mma<8>(acc, Ah, Al, Wm2h, Wm2l, 136, qr, qc);
        {
            float* g0 = agg + (size_t)d0 * 128;
            float* g1 = agg + (size_t)d1 * 128;
            #pragma unroll
            for (int nb = 0; nb < 16; nb++) {
                int col = 8 * nb + qc;
                if (v0)
                    asm volatile("red.global.add.v2.f32 [%0], {%1, %2};"
                                 :: "l"(g0 + col), "f"(acc[nb][0]), "f"(acc[nb][1]) : "memory");
                if (v1)
                    asm volatile("red.global.add.v2.f32 [%0], {%1, %2};"
                                 :: "l"(g1 + col), "f"(acc[nb][2]), "f"(acc[nb][3]) : "memory");
            }
        }
    }
}

// ================= LayerNorm + relu (+ agg re-zero for next layer) =================
__global__ void ln_kernel(float* __restrict__ agg, const float* __restrict__ deg,
                          const float* __restrict__ bm2, const float* __restrict__ lnw,
                          const float* __restrict__ lnb, float* __restrict__ xout, int N)
{
    int gwarp = (blockIdx.x * blockDim.x + threadIdx.x) >> 5;
    int lane = threadIdx.x & 31;
    if (gwarp >= N) return;
    float d = deg[gwarp];
    float inv = 1.f / fmaxf(d, 1.f);
    float add = (d > 0.f) ? 1.f : 0.f;
    float4 v = ((const float4*)agg)[(size_t)gwarp * 32 + lane];
    ((float4*)agg)[(size_t)gwarp * 32 + lane] = make_float4(0.f, 0.f, 0.f, 0.f);
    float4 b = ((const float4*)bm2)[lane];
    v.x = v.x * inv + add * b.x;
    v.y = v.y * inv + add * b.y;
    v.z = v.z * inv + add * b.z;
    v.w = v.w * inv + add * b.w;
    float s = v.x + v.y + v.z + v.w;
    #pragma unroll
    for (int o = 16; o; o >>= 1) s += __shfl_xor_sync(0xffffffffu, s, o);
    float mu = s * (1.f / 128.f);
    float d0 = v.x - mu, d1 = v.y - mu, d2 = v.z - mu, d3 = v.w - mu;
    float q = d0 * d0 + d1 * d1 + d2 * d2 + d3 * d3;
    #pragma unroll
    for (int o = 16; o; o >>= 1) q += __shfl_xor_sync(0xffffffffu, q, o);
    float rs = rsqrtf(q * (1.f / 128.f) + 1e-5f);
    float4 w = ((const float4*)lnw)[lane];
    float4 bb = ((const float4*)lnb)[lane];
    float4 o;
    o.x = fmaxf(d0 * rs * w.x + bb.x, 0.f);
    o.y = fmaxf(d1 * rs * w.y + bb.y, 0.f);
    o.z = fmaxf(d2 * rs * w.z + bb.z, 0.f);
    o.w = fmaxf(d3 * rs * w.w + bb.w, 0.f);
    ((float4*)xout)[(size_t)gwarp * 32 + lane] = o;
}

// ================= host =================
extern "C" void kernel_launch(void* const* d_in, const int* in_sizes, int n_in,
                              void* d_out, int out_size)
{
    const float* x    = (const float*)d_in[0];
    const float* ea   = (const float*)d_in[1];
    const int*   eidx = (const int*)  d_in[2];
    const float* Wn1  = (const float*)d_in[3];
    const float* bn1  = (const float*)d_in[4];
    const float* Wn2  = (const float*)d_in[5];
    const float* bn2  = (const float*)d_in[6];
    const float* We1  = (const float*)d_in[7];
    const float* be1  = (const float*)d_in[8];
    const float* We2  = (const float*)d_in[9];
    const float* be2  = (const float*)d_in[10];
    const float* Wm1  = (const float*)d_in[11];
    const float* bm1  = (const float*)d_in[12];
    const float* Wm2  = (const float*)d_in[13];
    const float* bm2  = (const float*)d_in[14];
    const float* lnw  = (const float*)d_in[15];
    const float* lnb  = (const float*)d_in[16];
    const float* Wf   = (const float*)d_in[17];
    const float* bf   = (const float*)d_in[18];

    int N = in_sizes[0] / 128;
    int E = in_sizes[1] / 64;
    const int* srcp = eidx;
    const int* dstp = eidx + E;

    float *h1n, *ab, *xb, *agg, *deg, *Wab, *Wc, *bc;
    uint4 *wpack, *wnode, *wf;
    cudaGetSymbolAddress((void**)&h1n, g_h1n);
    cudaGetSymbolAddress((void**)&ab,  g_ab);
    cudaGetSymbolAddress((void**)&xb,  g_x);
    cudaGetSymbolAddress((void**)&agg, g_agg);
    cudaGetSymbolAddress((void**)&deg, g_deg);
    cudaGetSymbolAddress((void**)&Wab, g_Wab);
    cudaGetSymbolAddress((void**)&Wc,  g_Wc);
    cudaGetSymbolAddress((void**)&bc,  g_bc);
    cudaGetSymbolAddress((void**)&wpack, g_wpack);
    cudaGetSymbolAddress((void**)&wnode, g_wnode);
    cudaGetSymbolAddress((void**)&wf, g_wf);
    __nv_bfloat16* wb = (__nv_bfloat16*)wpack;
    __nv_bfloat16* nbw = (__nv_bfloat16*)wnode;
    __nv_bfloat16* wfb = (__nv_bfloat16*)wf;

    cudaFuncSetAttribute(edge_kernel3, cudaFuncAttributeMaxDynamicSharedMemorySize,
                         EDGE3_SMEM);
    int smW1  = 2 * 128 * 136 * 2 + 512;   // ngemm<8,16>
    int smWab = 2 * 128 * 264 * 2 + 512;   // ngemm<16,16>
    int smWf  = 2 * 64 * 136 * 2 + 256;    // ngemm<8,8>
    cudaFuncSetAttribute(ngemm<8, 16, true>,   cudaFuncAttributeMaxDynamicSharedMemorySize, smW1);
    cudaFuncSetAttribute(ngemm<16, 16, false>, cudaFuncAttributeMaxDynamicSharedMemorySize, smWab);
    cudaFuncSetAttribute(ngemm<8, 8, false>,   cudaFuncAttributeMaxDynamicSharedMemorySize, smWf);

    zero_init<<<(N * 32 + 255) / 256, 256>>>(agg, deg, N);
    deg_kernel<<<(E + 255) / 256, 256>>>(dstp, deg, E);
    fuse_all<<<1008, 256>>>(Wn2, Wm1, We2, bn2, be2, bm1, Wab, Wc, bc);
    prep_all<<<1664, 256>>>(We1, Wc, Wm2, Wn1, Wab, Wf, wb, nbw, wfb);

    const float* curx = x;
    int gRows = (N + 127) / 128;
    for (int l = 0; l < LLAYERS; l++) {
        __nv_bfloat16* npb = nbw + (size_t)l * NP_LAYER_ELEMS;
        ngemm<8, 16, true><<<dim3(gRows, 2), 256, smW1>>>(
            curx, (const uint4*)(npb + NP_W1), bn1 + l * 256, h1n, N, 256);
        ngemm<16, 16, false><<<dim3(gRows, 2), 256, smWab>>>(
            h1n, (const uint4*)(npb + NP_WAB), (const float*)nullptr, ab, N, 256);
        edge_kernel3<<<148, 256, EDGE3_SMEM>>>(
            ea, srcp, dstp,
            (const uint4*)(wb + (size_t)l * WP_LAYER_ELEMS),
            be1 + l * 128, bc + l * 128, ab, agg, E);
        ln_kernel<<<(N + 7) / 8, 256>>>(agg, deg, bm2 + l * 128, lnw + l * 128,
                                        lnb + l * 128, xb, N);
        curx = xb;
    }
    ngemm<8, 8, false><<<dim3(gRows, 1), 256, smWf>>>(
        curx, (const uint4*)wfb, bf, (float*)d_out, N, 64);
}